// round 11
// baseline (speedup 1.0000x reference)
#include <cuda_runtime.h>
#include <math.h>

#define EPS 1e-7f
#define ONE_M_EPS (1.0f - 1e-7f)

// Problem constants (fixed shapes from setup_inputs)
#define NSEQ 512
#define DIM 512
#define NH 8
#define HD 64
#define NQB 16          // 512/32 query blocks

// Scratch (no allocation allowed; __device__ globals)
__device__ float g_scale[NSEQ];
__device__ float g_qkv[NSEQ * 3 * DIM];       // (N, 1536)
__device__ float g_qh[NH * NSEQ * HD];        // (H, N, 64)
__device__ float g_kh[NH * NSEQ * HD];
__device__ float g_q2[NH * NSEQ];
__device__ float g_k2[NH * NSEQ];
__device__ float g_attn[NSEQ * DIM];          // (N, 512): [n][h*64+d]
// split-K partials: tile ti = (h*16+qb)*16+kb
__device__ float g_po[NH * NQB * NQB * 32 * 64];   // 16.8 MB (L2-resident)
__device__ float g_pm[NH * NQB * NQB * 32];
__device__ float g_pl[NH * NQB * NQB * 32];

__device__ __forceinline__ float warp_sum(float v) {
#pragma unroll
    for (int s = 16; s; s >>= 1) v += __shfl_xor_sync(0xffffffffu, v, s);
    return v;
}
__device__ __forceinline__ float softplusf(float x) {
    return (x > 20.f) ? x : log1pf(__expf(x));
}

// ---------------------------------------------------------------------------
// Kernel A: logmap0 row scale.
// ---------------------------------------------------------------------------
__global__ void rowscale_kernel(const float* __restrict__ x,
                                const float* __restrict__ c_sphere) {
    int warp = threadIdx.x >> 5, lane = threadIdx.x & 31;
    int row = blockIdx.x * 8 + warp;
    const float4* xr = (const float4*)(x + row * DIM);
    float ss = 0.f;
#pragma unroll
    for (int q = 0; q < 4; q++) {
        float4 v = xr[lane + q * 32];
        ss += v.x * v.x + v.y * v.y + v.z * v.z + v.w * v.w;
    }
    ss = warp_sum(ss);
    if (lane == 0) {
        float yn = sqrtf(ss);
        float sc = fmaxf(sqrtf(c_sphere[0]), EPS);
        float s = 0.f;
        if (yn >= EPS)
            s = atanhf(fminf(yn, ONE_M_EPS)) / (sc * fmaxf(yn, EPS));
        g_scale[row] = s;
    }
}

// ---------------------------------------------------------------------------
// Tiled fp32 GEMM (R9 version — kept; it measured faster)
// ---------------------------------------------------------------------------
template <bool HAS_SCALE>
__global__ void gemm_kernel(const float* __restrict__ A, const float* __restrict__ B,
                            const float* __restrict__ bias,
                            const float* __restrict__ rowscale,
                            float* __restrict__ C, int M, int N, int K) {
    __shared__ float As[16][68];
    __shared__ float Bs[16][64];
    int tid = threadIdx.x;
    int tx = tid & 15, ty = tid >> 4;
    int m0 = blockIdx.y * 64, n0 = blockIdx.x * 64;
    int aRow = tid >> 2, aCol = (tid & 3) * 4;
    int bRow = tid >> 4, bCol = (tid & 15) * 4;
    float acc[4][4] = {};
    float ascale = 1.f;
    if (HAS_SCALE) ascale = rowscale[m0 + aRow];

    for (int kb = 0; kb < K; kb += 16) {
        float4 a4 = *(const float4*)(A + (size_t)(m0 + aRow) * K + kb + aCol);
        if (HAS_SCALE) { a4.x *= ascale; a4.y *= ascale; a4.z *= ascale; a4.w *= ascale; }
        As[aCol + 0][aRow] = a4.x;
        As[aCol + 1][aRow] = a4.y;
        As[aCol + 2][aRow] = a4.z;
        As[aCol + 3][aRow] = a4.w;
        *(float4*)&Bs[bRow][bCol] =
            *(const float4*)(B + (size_t)(kb + bRow) * N + n0 + bCol);
        __syncthreads();
#pragma unroll
        for (int k = 0; k < 16; k++) {
            float4 av = *(float4*)&As[k][ty * 4];
            float4 b4 = *(float4*)&Bs[k][tx * 4];
            acc[0][0] += av.x * b4.x; acc[0][1] += av.x * b4.y; acc[0][2] += av.x * b4.z; acc[0][3] += av.x * b4.w;
            acc[1][0] += av.y * b4.x; acc[1][1] += av.y * b4.y; acc[1][2] += av.y * b4.z; acc[1][3] += av.y * b4.w;
            acc[2][0] += av.z * b4.x; acc[2][1] += av.z * b4.y; acc[2][2] += av.z * b4.z; acc[2][3] += av.z * b4.w;
            acc[3][0] += av.w * b4.x; acc[3][1] += av.w * b4.y; acc[3][2] += av.w * b4.z; acc[3][3] += av.w * b4.w;
        }
        __syncthreads();
    }
    float4 bv = *(const float4*)(bias + n0 + tx * 4);
#pragma unroll
    for (int i = 0; i < 4; i++) {
        float4 o;
        o.x = acc[i][0] + bv.x;
        o.y = acc[i][1] + bv.y;
        o.z = acc[i][2] + bv.z;
        o.w = acc[i][3] + bv.w;
        *(float4*)(C + (size_t)(m0 + ty * 4 + i) * N + n0 + tx * 4) = o;
    }
}

// ---------------------------------------------------------------------------
// Kernel C: RoPE + expmap0 + norms (unchanged)
// ---------------------------------------------------------------------------
__global__ void rope_expmap_kernel(const float* __restrict__ freqs,
                                   const float* __restrict__ c_logits) {
    int warp = threadIdx.x >> 5, lane = threadIdx.x & 31;
    int idx = blockIdx.x * 8 + warp;   // 0..4095
    int h = idx & 7, n = idx >> 3;
    float c = softplusf(c_logits[h]);
    float sc = fmaxf(sqrtf(c), EPS);
    float f = freqs[n * 32 + lane];
    float cs = cosf(f), sn = sinf(f);
    const float* base = g_qkv + (size_t)n * 1536 + h * 64;
#pragma unroll
    for (int w = 0; w < 2; w++) {   // w=0: q, w=1: k
        const float* src = base + w * DIM;
        float xr = src[lane], xi = src[lane + 32];
        float r0 = xr * cs - xi * sn;
        float r1 = xr * sn + xi * cs;
        float vn = sqrtf(warp_sum(r0 * r0 + r1 * r1));
        float mag = tanhf(sc * vn) / sc;
        float s = (vn < EPS) ? 0.f : mag / fmaxf(vn, EPS);
        if (mag >= 1.0f) s *= ONE_M_EPS / fmaxf(mag, EPS);  // _project
        float o0 = r0 * s, o1 = r1 * s;
        float x2 = warp_sum(o0 * o0 + o1 * o1);
        float* dst = (w == 0 ? g_qh : g_kh) + (size_t)(h * NSEQ + n) * HD;
        dst[lane] = o0;
        dst[lane + 32] = o1;
        if (lane == 0) (w == 0 ? g_q2 : g_k2)[h * NSEQ + n] = x2;
    }
}

// ---------------------------------------------------------------------------
// Kernel D v3, pass 1: split-K partial attention.
// grid (136, 8): blockIdx.x = triangular tile index (qb,kb), kb <= qb.
// Each CTA: one 32x32 score tile -> local softmax partials (m, l, p.V).
// ---------------------------------------------------------------------------
__device__ __forceinline__ float hyp_score(float dot, float q2, float k2, float b,
                                           float c, float c2, float sc,
                                           float neg_gs2sc) {
    float xy = -dot;
    float t2 = 2.f * c * xy;
    float a = 1.f + t2 + c * k2;
    float den = 1.f + t2 + c2 * q2 * k2;
    float num2 = fmaxf(a * a * q2 + 2.f * a * b * xy + b * b * k2, 0.f);
    float nrm = sqrtf(num2) / fmaxf(den, EPS);
    if (nrm >= 1.f) nrm = ONE_M_EPS;                    // _project
    float arg = fminf(sc * nrm, ONE_M_EPS);
    float at = 0.5f * __logf(__fdividef(1.f + arg, 1.f - arg));
    return neg_gs2sc * at;
}

__global__ __launch_bounds__(256) void attn_part_kernel(const float* __restrict__ c_logits,
                                                        const float* __restrict__ geo_scale) {
    __shared__ float Qs[32][68];
    __shared__ float Ks[32][68];
    __shared__ float Vs[32][68];
    __shared__ float Ss[32][36];
    __shared__ float q2s[32], k2s[32], bs[32];

    int tid = threadIdx.x;
    int lane = tid & 31, warp = tid >> 5;
    int h = blockIdx.y;
    int t = blockIdx.x;
    // triangular decode with integer fixup
    int qb = (int)floorf((sqrtf(8.f * t + 1.f) - 1.f) * 0.5f);
    while ((qb + 1) * (qb + 2) / 2 <= t) qb++;
    while (qb * (qb + 1) / 2 > t) qb--;
    int kb = t - qb * (qb + 1) / 2;

    float c = softplusf(c_logits[h]);
    float sc = fmaxf(sqrtf(c), EPS);
    float gs = geo_scale[h];
    float c2 = c * c;
    float neg_gs2sc = -gs * 2.0f / sc;

    // ---- stage Q, K, V, stats ----
    {
        const float* qbase = g_qh + ((size_t)h * NSEQ + qb * 32) * HD;
        const float* kbase = g_kh + ((size_t)h * NSEQ + kb * 32) * HD;
        const float* vbase = g_qkv + (size_t)(kb * 32) * 1536 + 2 * DIM + h * 64;
#pragma unroll
        for (int e = tid; e < 512; e += 256) {       // float4 units
            int row = e >> 4, dc = e & 15;
            *(float4*)&Qs[row][dc * 4] = *(const float4*)(qbase + row * 64 + dc * 4);
            *(float4*)&Ks[row][dc * 4] = *(const float4*)(kbase + row * 64 + dc * 4);
            *(float4*)&Vs[row][dc * 4] = *(const float4*)(vbase + (size_t)row * 1536 + dc * 4);
        }
        if (tid < 32) {
            float q2 = g_q2[h * NSEQ + qb * 32 + tid];
            q2s[tid] = q2;
            bs[tid] = 1.f - c * q2;
            k2s[tid] = g_k2[h * NSEQ + kb * 32 + tid];
        }
    }
    __syncthreads();

    // ---- score phase: 2x2 micro-tile over 64 dims ----
    int ty = tid >> 4, tx = tid & 15;
    float d00 = 0.f, d01 = 0.f, d10 = 0.f, d11 = 0.f;
#pragma unroll
    for (int dc = 0; dc < 16; dc++) {
        float4 qa = *(float4*)&Qs[ty][dc * 4];
        float4 qc = *(float4*)&Qs[ty + 16][dc * 4];
        float4 ka = *(float4*)&Ks[tx][dc * 4];
        float4 kc = *(float4*)&Ks[tx + 16][dc * 4];
        d00 += qa.x * ka.x + qa.y * ka.y + qa.z * ka.z + qa.w * ka.w;
        d01 += qa.x * kc.x + qa.y * kc.y + qa.z * kc.z + qa.w * kc.w;
        d10 += qc.x * ka.x + qc.y * ka.y + qc.z * ka.z + qc.w * ka.w;
        d11 += qc.x * kc.x + qc.y * kc.y + qc.z * kc.z + qc.w * kc.w;
    }
    {
        int qg0 = qb * 32 + ty, qg1 = qg0 + 16;
        int jg0 = kb * 32 + tx, jg1 = jg0 + 16;
        float q2a = q2s[ty], q2b = q2s[ty + 16];
        float ba = bs[ty], bb = bs[ty + 16];
        float k2a = k2s[tx], k2b = k2s[tx + 16];
        Ss[ty][tx]           = (jg0 <= qg0) ? hyp_score(d00, q2a, k2a, ba, c, c2, sc, neg_gs2sc) : -INFINITY;
        Ss[ty][tx + 16]      = (jg1 <= qg0) ? hyp_score(d01, q2a, k2b, ba, c, c2, sc, neg_gs2sc) : -INFINITY;
        Ss[ty + 16][tx]      = (jg0 <= qg1) ? hyp_score(d10, q2b, k2a, bb, c, c2, sc, neg_gs2sc) : -INFINITY;
        Ss[ty + 16][tx + 16] = (jg1 <= qg1) ? hyp_score(d11, q2b, k2b, bb, c, c2, sc, neg_gs2sc) : -INFINITY;
    }
    __syncthreads();

    int ti = (h * NQB + qb) * NQB + kb;

    // ---- local softmax: 8 lanes per row; write m, l, p ----
    {
        int sr = (warp << 2) + (lane >> 3), part = lane & 7;
        float4 s4 = *(float4*)&Ss[sr][part * 4];
        float mx = fmaxf(fmaxf(s4.x, s4.y), fmaxf(s4.z, s4.w));
#pragma unroll
        for (int d = 1; d < 8; d <<= 1)
            mx = fmaxf(mx, __shfl_xor_sync(0xffffffffu, mx, d));
        float4 p4;
        p4.x = __expf(s4.x - mx);
        p4.y = __expf(s4.y - mx);
        p4.z = __expf(s4.z - mx);
        p4.w = __expf(s4.w - mx);
        float ps = p4.x + p4.y + p4.z + p4.w;
#pragma unroll
        for (int d = 1; d < 8; d <<= 1)
            ps += __shfl_xor_sync(0xffffffffu, ps, d);
        *(float4*)&Ss[sr][part * 4] = p4;
        if (part == 0) {
            g_pm[ti * 32 + sr] = mx;
            g_pl[ti * 32 + sr] = ps;
        }
    }
    __syncthreads();

    // ---- PV partial: thread owns (row pr, dims pc*4.. & 32+pc*4..) ----
    {
        int pr = tid >> 3, pc = tid & 7;
        float4 oA = {0.f, 0.f, 0.f, 0.f}, oB = {0.f, 0.f, 0.f, 0.f};
#pragma unroll
        for (int jj = 0; jj < 32; jj++) {
            float p = Ss[pr][jj];
            float4 v0 = *(float4*)&Vs[jj][pc * 4];
            float4 v1 = *(float4*)&Vs[jj][32 + pc * 4];
            oA.x += p * v0.x; oA.y += p * v0.y; oA.z += p * v0.z; oA.w += p * v0.w;
            oB.x += p * v1.x; oB.y += p * v1.y; oB.z += p * v1.z; oB.w += p * v1.w;
        }
        float* dst = g_po + (size_t)ti * 2048 + pr * 64;
        *(float4*)(dst + pc * 4) = oA;
        *(float4*)(dst + 32 + pc * 4) = oB;
    }
}

// ---------------------------------------------------------------------------
// Kernel D v3, pass 2: combine partials.  grid (16, 8), 256 threads.
// o(h,qb) = sum_kb exp(m_kb - M) * po_kb / sum_kb exp(m_kb - M) * l_kb
// ---------------------------------------------------------------------------
__global__ __launch_bounds__(256) void attn_reduce_kernel() {
    int tid = threadIdx.x;
    int qb = blockIdx.x, h = blockIdx.y;
    int pr = tid >> 3, pc = tid & 7;
    int nk = qb + 1;
    int tibase = (h * NQB + qb) * NQB;

    float mv[NQB];
    float M = -INFINITY;
    for (int kb = 0; kb < nk; kb++) {
        mv[kb] = g_pm[(tibase + kb) * 32 + pr];
        M = fmaxf(M, mv[kb]);
    }
    float L = 0.f;
    float4 oA = {0.f, 0.f, 0.f, 0.f}, oB = {0.f, 0.f, 0.f, 0.f};
    for (int kb = 0; kb < nk; kb++) {
        float w = __expf(mv[kb] - M);
        L += w * g_pl[(tibase + kb) * 32 + pr];
        const float* src = g_po + (size_t)(tibase + kb) * 2048 + pr * 64;
        float4 a = *(const float4*)(src + pc * 4);
        float4 b = *(const float4*)(src + 32 + pc * 4);
        oA.x += w * a.x; oA.y += w * a.y; oA.z += w * a.z; oA.w += w * a.w;
        oB.x += w * b.x; oB.y += w * b.y; oB.z += w * b.z; oB.w += w * b.w;
    }
    float invl = __frcp_rn(L);
    int n = qb * 32 + pr;
    float* dst = g_attn + (size_t)n * DIM + h * 64;
    oA.x *= invl; oA.y *= invl; oA.z *= invl; oA.w *= invl;
    oB.x *= invl; oB.y *= invl; oB.z *= invl; oB.w *= invl;
    *(float4*)(dst + pc * 4) = oA;
    *(float4*)(dst + 32 + pc * 4) = oB;
}

// ---------------------------------------------------------------------------
extern "C" void kernel_launch(void* const* d_in, const int* in_sizes, int n_in,
                              void* d_out, int out_size) {
    const float* x_hyp    = (const float*)d_in[0];
    const float* freqs    = (const float*)d_in[1];
    const float* c_sphere = (const float*)d_in[2];
    const float* w_qkv    = (const float*)d_in[3];
    const float* b_qkv    = (const float*)d_in[4];
    const float* w_out    = (const float*)d_in[5];
    const float* b_out    = (const float*)d_in[6];
    const float* c_logits = (const float*)d_in[7];
    const float* geo      = (const float*)d_in[8];
    float* out = (float*)d_out;

    void *p_qkv = nullptr, *p_attn = nullptr, *p_scale = nullptr;
    cudaGetSymbolAddress(&p_qkv, g_qkv);
    cudaGetSymbolAddress(&p_attn, g_attn);
    cudaGetSymbolAddress(&p_scale, g_scale);

    // 1. logmap0 row scales
    rowscale_kernel<<<64, 256>>>(x_hyp, c_sphere);
    // 2. qkv = (x_hyp * scale) @ w_qkv + b_qkv   (M=512, N=1536, K=512)
    gemm_kernel<true><<<dim3(24, 8), 256>>>(x_hyp, w_qkv, b_qkv,
                                            (const float*)p_scale,
                                            (float*)p_qkv, NSEQ, 3 * DIM, DIM);
    // 3. RoPE + expmap0 + norms
    rope_expmap_kernel<<<512, 256>>>(freqs, c_logits);
    // 4a. split-K partial attention (136 causal tiles x 8 heads)
    attn_part_kernel<<<dim3(136, 8), 256>>>(c_logits, geo);
    // 4b. combine partials
    attn_reduce_kernel<<<dim3(16, 8), 256>>>();
    // 5. out = attn_out @ w_out + b_out   (M=N=K=512)
    gemm_kernel<false><<<dim3(8, 8), 256>>>((const float*)p_attn, w_out, b_out,
                                            nullptr, out, NSEQ, DIM, DIM);
}

// round 14
// speedup vs baseline: 1.5712x; 1.5712x over previous
#include <cuda_runtime.h>
#include <math.h>

#define EPS 1e-7f
#define ONE_M_EPS (1.0f - 1e-7f)

// Problem constants (fixed shapes from setup_inputs)
#define NSEQ 512
#define DIM 512
#define NH 8
#define HD 64
#define NQB 16          // 512/32 query blocks

// Scratch (no allocation allowed; __device__ globals)
__device__ float g_scale[NSEQ];
__device__ float g_qkv[NSEQ * 3 * DIM];       // (N, 1536)
__device__ float g_qh[NH * NSEQ * HD];        // (H, N, 64)
__device__ float g_kh[NH * NSEQ * HD];
__device__ float g_q2[NH * NSEQ];
__device__ float g_k2[NH * NSEQ];
__device__ float g_attn[NSEQ * DIM];          // (N, 512): [n][h*64+d]
// split-K partials: tile ti = (h*16+qb)*16+kb; entries with kb>qb are never
// written and stay zero (BSS zero-init), so predicated-zero weights are safe.
__device__ float g_po[NH * NQB * NQB * 32 * 64];   // 16.8 MB (L2-resident)
__device__ float g_pm[NH * NQB * NQB * 32];
__device__ float g_pl[NH * NQB * NQB * 32];

__device__ __forceinline__ float warp_sum(float v) {
#pragma unroll
    for (int s = 16; s; s >>= 1) v += __shfl_xor_sync(0xffffffffu, v, s);
    return v;
}
__device__ __forceinline__ float softplusf(float x) {
    return (x > 20.f) ? x : log1pf(__expf(x));
}

// ---------------------------------------------------------------------------
// Kernel A: logmap0 row scale.
// ---------------------------------------------------------------------------
__global__ void rowscale_kernel(const float* __restrict__ x,
                                const float* __restrict__ c_sphere) {
    int warp = threadIdx.x >> 5, lane = threadIdx.x & 31;
    int row = blockIdx.x * 8 + warp;
    const float4* xr = (const float4*)(x + row * DIM);
    float ss = 0.f;
#pragma unroll
    for (int q = 0; q < 4; q++) {
        float4 v = xr[lane + q * 32];
        ss += v.x * v.x + v.y * v.y + v.z * v.z + v.w * v.w;
    }
    ss = warp_sum(ss);
    if (lane == 0) {
        float yn = sqrtf(ss);
        float sc = fmaxf(sqrtf(c_sphere[0]), EPS);
        float s = 0.f;
        if (yn >= EPS)
            s = atanhf(fminf(yn, ONE_M_EPS)) / (sc * fmaxf(yn, EPS));
        g_scale[row] = s;
    }
}

// ---------------------------------------------------------------------------
// Tiled fp32 GEMM (R9 version — kept; it measured faster)
// ---------------------------------------------------------------------------
template <bool HAS_SCALE>
__global__ void gemm_kernel(const float* __restrict__ A, const float* __restrict__ B,
                            const float* __restrict__ bias,
                            const float* __restrict__ rowscale,
                            float* __restrict__ C, int M, int N, int K) {
    __shared__ float As[16][68];
    __shared__ float Bs[16][64];
    int tid = threadIdx.x;
    int tx = tid & 15, ty = tid >> 4;
    int m0 = blockIdx.y * 64, n0 = blockIdx.x * 64;
    int aRow = tid >> 2, aCol = (tid & 3) * 4;
    int bRow = tid >> 4, bCol = (tid & 15) * 4;
    float acc[4][4] = {};
    float ascale = 1.f;
    if (HAS_SCALE) ascale = rowscale[m0 + aRow];

    for (int kb = 0; kb < K; kb += 16) {
        float4 a4 = *(const float4*)(A + (size_t)(m0 + aRow) * K + kb + aCol);
        if (HAS_SCALE) { a4.x *= ascale; a4.y *= ascale; a4.z *= ascale; a4.w *= ascale; }
        As[aCol + 0][aRow] = a4.x;
        As[aCol + 1][aRow] = a4.y;
        As[aCol + 2][aRow] = a4.z;
        As[aCol + 3][aRow] = a4.w;
        *(float4*)&Bs[bRow][bCol] =
            *(const float4*)(B + (size_t)(kb + bRow) * N + n0 + bCol);
        __syncthreads();
#pragma unroll
        for (int k = 0; k < 16; k++) {
            float4 av = *(float4*)&As[k][ty * 4];
            float4 b4 = *(float4*)&Bs[k][tx * 4];
            acc[0][0] += av.x * b4.x; acc[0][1] += av.x * b4.y; acc[0][2] += av.x * b4.z; acc[0][3] += av.x * b4.w;
            acc[1][0] += av.y * b4.x; acc[1][1] += av.y * b4.y; acc[1][2] += av.y * b4.z; acc[1][3] += av.y * b4.w;
            acc[2][0] += av.z * b4.x; acc[2][1] += av.z * b4.y; acc[2][2] += av.z * b4.z; acc[2][3] += av.z * b4.w;
            acc[3][0] += av.w * b4.x; acc[3][1] += av.w * b4.y; acc[3][2] += av.w * b4.z; acc[3][3] += av.w * b4.w;
        }
        __syncthreads();
    }
    float4 bv = *(const float4*)(bias + n0 + tx * 4);
#pragma unroll
    for (int i = 0; i < 4; i++) {
        float4 o;
        o.x = acc[i][0] + bv.x;
        o.y = acc[i][1] + bv.y;
        o.z = acc[i][2] + bv.z;
        o.w = acc[i][3] + bv.w;
        *(float4*)(C + (size_t)(m0 + ty * 4 + i) * N + n0 + tx * 4) = o;
    }
}

// ---------------------------------------------------------------------------
// Kernel C: RoPE + expmap0 + norms (unchanged)
// ---------------------------------------------------------------------------
__global__ void rope_expmap_kernel(const float* __restrict__ freqs,
                                   const float* __restrict__ c_logits) {
    int warp = threadIdx.x >> 5, lane = threadIdx.x & 31;
    int idx = blockIdx.x * 8 + warp;   // 0..4095
    int h = idx & 7, n = idx >> 3;
    float c = softplusf(c_logits[h]);
    float sc = fmaxf(sqrtf(c), EPS);
    float f = freqs[n * 32 + lane];
    float cs = cosf(f), sn = sinf(f);
    const float* base = g_qkv + (size_t)n * 1536 + h * 64;
#pragma unroll
    for (int w = 0; w < 2; w++) {   // w=0: q, w=1: k
        const float* src = base + w * DIM;
        float xr = src[lane], xi = src[lane + 32];
        float r0 = xr * cs - xi * sn;
        float r1 = xr * sn + xi * cs;
        float vn = sqrtf(warp_sum(r0 * r0 + r1 * r1));
        float mag = tanhf(sc * vn) / sc;
        float s = (vn < EPS) ? 0.f : mag / fmaxf(vn, EPS);
        if (mag >= 1.0f) s *= ONE_M_EPS / fmaxf(mag, EPS);  // _project
        float o0 = r0 * s, o1 = r1 * s;
        float x2 = warp_sum(o0 * o0 + o1 * o1);
        float* dst = (w == 0 ? g_qh : g_kh) + (size_t)(h * NSEQ + n) * HD;
        dst[lane] = o0;
        dst[lane + 32] = o1;
        if (lane == 0) (w == 0 ? g_q2 : g_k2)[h * NSEQ + n] = x2;
    }
}

// ---------------------------------------------------------------------------
// Kernel D v3, pass 1: split-K partial attention. (byte-identical to R11 —
// measured 36.2us, occ 43.6%, issue 48.2%)
// ---------------------------------------------------------------------------
__device__ __forceinline__ float hyp_score(float dot, float q2, float k2, float b,
                                           float c, float c2, float sc,
                                           float neg_gs2sc) {
    float xy = -dot;
    float t2 = 2.f * c * xy;
    float a = 1.f + t2 + c * k2;
    float den = 1.f + t2 + c2 * q2 * k2;
    float num2 = fmaxf(a * a * q2 + 2.f * a * b * xy + b * b * k2, 0.f);
    float nrm = sqrtf(num2) / fmaxf(den, EPS);
    if (nrm >= 1.f) nrm = ONE_M_EPS;                    // _project
    float arg = fminf(sc * nrm, ONE_M_EPS);
    float at = 0.5f * __logf(__fdividef(1.f + arg, 1.f - arg));
    return neg_gs2sc * at;
}

__global__ __launch_bounds__(256) void attn_part_kernel(const float* __restrict__ c_logits,
                                                        const float* __restrict__ geo_scale) {
    __shared__ float Qs[32][68];
    __shared__ float Ks[32][68];
    __shared__ float Vs[32][68];
    __shared__ float Ss[32][36];
    __shared__ float q2s[32], k2s[32], bs[32];

    int tid = threadIdx.x;
    int lane = tid & 31, warp = tid >> 5;
    int h = blockIdx.y;
    int t = blockIdx.x;
    // triangular decode with integer fixup
    int qb = (int)floorf((sqrtf(8.f * t + 1.f) - 1.f) * 0.5f);
    while ((qb + 1) * (qb + 2) / 2 <= t) qb++;
    while (qb * (qb + 1) / 2 > t) qb--;
    int kb = t - qb * (qb + 1) / 2;

    float c = softplusf(c_logits[h]);
    float sc = fmaxf(sqrtf(c), EPS);
    float gs = geo_scale[h];
    float c2 = c * c;
    float neg_gs2sc = -gs * 2.0f / sc;

    // ---- stage Q, K, V, stats ----
    {
        const float* qbase = g_qh + ((size_t)h * NSEQ + qb * 32) * HD;
        const float* kbase = g_kh + ((size_t)h * NSEQ + kb * 32) * HD;
        const float* vbase = g_qkv + (size_t)(kb * 32) * 1536 + 2 * DIM + h * 64;
#pragma unroll
        for (int e = tid; e < 512; e += 256) {       // float4 units
            int row = e >> 4, dc = e & 15;
            *(float4*)&Qs[row][dc * 4] = *(const float4*)(qbase + row * 64 + dc * 4);
            *(float4*)&Ks[row][dc * 4] = *(const float4*)(kbase + row * 64 + dc * 4);
            *(float4*)&Vs[row][dc * 4] = *(const float4*)(vbase + (size_t)row * 1536 + dc * 4);
        }
        if (tid < 32) {
            float q2 = g_q2[h * NSEQ + qb * 32 + tid];
            q2s[tid] = q2;
            bs[tid] = 1.f - c * q2;
            k2s[tid] = g_k2[h * NSEQ + kb * 32 + tid];
        }
    }
    __syncthreads();

    // ---- score phase: 2x2 micro-tile over 64 dims ----
    int ty = tid >> 4, tx = tid & 15;
    float d00 = 0.f, d01 = 0.f, d10 = 0.f, d11 = 0.f;
#pragma unroll
    for (int dc = 0; dc < 16; dc++) {
        float4 qa = *(float4*)&Qs[ty][dc * 4];
        float4 qc = *(float4*)&Qs[ty + 16][dc * 4];
        float4 ka = *(float4*)&Ks[tx][dc * 4];
        float4 kc = *(float4*)&Ks[tx + 16][dc * 4];
        d00 += qa.x * ka.x + qa.y * ka.y + qa.z * ka.z + qa.w * ka.w;
        d01 += qa.x * kc.x + qa.y * kc.y + qa.z * kc.z + qa.w * kc.w;
        d10 += qc.x * ka.x + qc.y * ka.y + qc.z * ka.z + qc.w * ka.w;
        d11 += qc.x * kc.x + qc.y * kc.y + qc.z * kc.z + qc.w * kc.w;
    }
    {
        int qg0 = qb * 32 + ty, qg1 = qg0 + 16;
        int jg0 = kb * 32 + tx, jg1 = jg0 + 16;
        float q2a = q2s[ty], q2b = q2s[ty + 16];
        float ba = bs[ty], bb = bs[ty + 16];
        float k2a = k2s[tx], k2b = k2s[tx + 16];
        Ss[ty][tx]           = (jg0 <= qg0) ? hyp_score(d00, q2a, k2a, ba, c, c2, sc, neg_gs2sc) : -INFINITY;
        Ss[ty][tx + 16]      = (jg1 <= qg0) ? hyp_score(d01, q2a, k2b, ba, c, c2, sc, neg_gs2sc) : -INFINITY;
        Ss[ty + 16][tx]      = (jg0 <= qg1) ? hyp_score(d10, q2b, k2a, bb, c, c2, sc, neg_gs2sc) : -INFINITY;
        Ss[ty + 16][tx + 16] = (jg1 <= qg1) ? hyp_score(d11, q2b, k2b, bb, c, c2, sc, neg_gs2sc) : -INFINITY;
    }
    __syncthreads();

    int ti = (h * NQB + qb) * NQB + kb;

    // ---- local softmax: 8 lanes per row; write m, l, p ----
    {
        int sr = (warp << 2) + (lane >> 3), part = lane & 7;
        float4 s4 = *(float4*)&Ss[sr][part * 4];
        float mx = fmaxf(fmaxf(s4.x, s4.y), fmaxf(s4.z, s4.w));
#pragma unroll
        for (int d = 1; d < 8; d <<= 1)
            mx = fmaxf(mx, __shfl_xor_sync(0xffffffffu, mx, d));
        float4 p4;
        p4.x = __expf(s4.x - mx);
        p4.y = __expf(s4.y - mx);
        p4.z = __expf(s4.z - mx);
        p4.w = __expf(s4.w - mx);
        float ps = p4.x + p4.y + p4.z + p4.w;
#pragma unroll
        for (int d = 1; d < 8; d <<= 1)
            ps += __shfl_xor_sync(0xffffffffu, ps, d);
        *(float4*)&Ss[sr][part * 4] = p4;
        if (part == 0) {
            g_pm[ti * 32 + sr] = mx;
            g_pl[ti * 32 + sr] = ps;
        }
    }
    __syncthreads();

    // ---- PV partial: thread owns (row pr, dims pc*4.. & 32+pc*4..) ----
    {
        int pr = tid >> 3, pc = tid & 7;
        float4 oA = {0.f, 0.f, 0.f, 0.f}, oB = {0.f, 0.f, 0.f, 0.f};
#pragma unroll
        for (int jj = 0; jj < 32; jj++) {
            float p = Ss[pr][jj];
            float4 v0 = *(float4*)&Vs[jj][pc * 4];
            float4 v1 = *(float4*)&Vs[jj][32 + pc * 4];
            oA.x += p * v0.x; oA.y += p * v0.y; oA.z += p * v0.z; oA.w += p * v0.w;
            oB.x += p * v1.x; oB.y += p * v1.y; oB.z += p * v1.z; oB.w += p * v1.w;
        }
        float* dst = g_po + (size_t)ti * 2048 + pr * 64;
        *(float4*)(dst + pc * 4) = oA;
        *(float4*)(dst + 32 + pc * 4) = oB;
    }
}

// ---------------------------------------------------------------------------
// Kernel D v3, pass 2 (v2): combine partials, FULLY UNROLLED.
// Fixed trip count NQB=16 with predicated weights -> mv[]/w[] stay in
// registers (no local-memory spill), all loads issue with high MLP.
// Unwritten partial slots (kb>qb) are zero-filled BSS and get weight 0.
// ---------------------------------------------------------------------------
__global__ __launch_bounds__(256) void attn_reduce_kernel() {
    int tid = threadIdx.x;
    int qb = blockIdx.x, h = blockIdx.y;
    int pr = tid >> 3, pc = tid & 7;
    int tibase = (h * NQB + qb) * NQB;

    float mv[NQB], lv[NQB];
#pragma unroll
    for (int kb = 0; kb < NQB; kb++) {
        mv[kb] = g_pm[(tibase + kb) * 32 + pr];    // always in-bounds
        lv[kb] = g_pl[(tibase + kb) * 32 + pr];
    }
    float M = -INFINITY;
#pragma unroll
    for (int kb = 0; kb < NQB; kb++)
        M = fmaxf(M, (kb <= qb) ? mv[kb] : -INFINITY);

    float w[NQB];
    float L = 0.f;
#pragma unroll
    for (int kb = 0; kb < NQB; kb++) {
        w[kb] = (kb <= qb) ? __expf(mv[kb] - M) : 0.f;
        L += w[kb] * lv[kb];
    }

    float4 oA = {0.f, 0.f, 0.f, 0.f}, oB = {0.f, 0.f, 0.f, 0.f};
#pragma unroll
    for (int kb = 0; kb < NQB; kb++) {
        const float* src = g_po + (size_t)(tibase + kb) * 2048 + pr * 64;
        float4 a = *(const float4*)(src + pc * 4);
        float4 b = *(const float4*)(src + 32 + pc * 4);
        float ww = w[kb];
        oA.x += ww * a.x; oA.y += ww * a.y; oA.z += ww * a.z; oA.w += ww * a.w;
        oB.x += ww * b.x; oB.y += ww * b.y; oB.z += ww * b.z; oB.w += ww * b.w;
    }

    float invl = __frcp_rn(L);
    int n = qb * 32 + pr;
    float* dst = g_attn + (size_t)n * DIM + h * 64;
    oA.x *= invl; oA.y *= invl; oA.z *= invl; oA.w *= invl;
    oB.x *= invl; oB.y *= invl; oB.z *= invl; oB.w *= invl;
    *(float4*)(dst + pc * 4) = oA;
    *(float4*)(dst + 32 + pc * 4) = oB;
}

// ---------------------------------------------------------------------------
extern "C" void kernel_launch(void* const* d_in, const int* in_sizes, int n_in,
                              void* d_out, int out_size) {
    const float* x_hyp    = (const float*)d_in[0];
    const float* freqs    = (const float*)d_in[1];
    const float* c_sphere = (const float*)d_in[2];
    const float* w_qkv    = (const float*)d_in[3];
    const float* b_qkv    = (const float*)d_in[4];
    const float* w_out    = (const float*)d_in[5];
    const float* b_out    = (const float*)d_in[6];
    const float* c_logits = (const float*)d_in[7];
    const float* geo      = (const float*)d_in[8];
    float* out = (float*)d_out;

    void *p_qkv = nullptr, *p_attn = nullptr, *p_scale = nullptr;
    cudaGetSymbolAddress(&p_qkv, g_qkv);
    cudaGetSymbolAddress(&p_attn, g_attn);
    cudaGetSymbolAddress(&p_scale, g_scale);

    // 1. logmap0 row scales
    rowscale_kernel<<<64, 256>>>(x_hyp, c_sphere);
    // 2. qkv = (x_hyp * scale) @ w_qkv + b_qkv   (M=512, N=1536, K=512)
    gemm_kernel<true><<<dim3(24, 8), 256>>>(x_hyp, w_qkv, b_qkv,
                                            (const float*)p_scale,
                                            (float*)p_qkv, NSEQ, 3 * DIM, DIM);
    // 3. RoPE + expmap0 + norms
    rope_expmap_kernel<<<512, 256>>>(freqs, c_logits);
    // 4a. split-K partial attention (136 causal tiles x 8 heads)
    attn_part_kernel<<<dim3(136, 8), 256>>>(c_logits, geo);
    // 4b. combine partials (fully unrolled)
    attn_reduce_kernel<<<dim3(16, 8), 256>>>();
    // 5. out = attn_out @ w_out + b_out   (M=N=K=512)
    gemm_kernel<false><<<dim3(8, 8), 256>>>((const float*)p_attn, w_out, b_out,
                                            nullptr, out, NSEQ, DIM, DIM);
}

// round 17
// speedup vs baseline: 1.6106x; 1.0250x over previous
#include <cuda_runtime.h>
#include <math.h>

#define EPS 1e-7f
#define ONE_M_EPS (1.0f - 1e-7f)

// Problem constants (fixed shapes from setup_inputs)
#define NSEQ 512
#define DIM 512
#define NH 8
#define HD 64
#define NQB 16          // 512/32 query blocks

typedef unsigned long long u64;

// ---- packed fp32x2 helpers (Blackwell FFMA2; bit-identical to 2x FFMA) ----
__device__ __forceinline__ u64 pack2(float lo, float hi) {
    u64 r; asm("mov.b64 %0, {%1, %2};" : "=l"(r) : "f"(lo), "f"(hi)); return r;
}
__device__ __forceinline__ void unpack2(u64 v, float& lo, float& hi) {
    asm("mov.b64 {%0, %1}, %2;" : "=f"(lo), "=f"(hi) : "l"(v));
}
__device__ __forceinline__ u64 ffma2(u64 a, u64 b, u64 c) {
    u64 d; asm("fma.rn.f32x2 %0, %1, %2, %3;" : "=l"(d) : "l"(a), "l"(b), "l"(c)); return d;
}

// Scratch (no allocation allowed; __device__ globals)
__device__ float g_scale[NSEQ];
__device__ float g_qkv[NSEQ * 3 * DIM];       // (N, 1536)
__device__ float g_qh[NH * NSEQ * HD];        // (H, N, 64)
__device__ float g_kh[NH * NSEQ * HD];
__device__ float g_q2[NH * NSEQ];
__device__ float g_k2[NH * NSEQ];
__device__ float g_attn[NSEQ * DIM];          // (N, 512): [n][h*64+d]
// split-K partials: tile ti = (h*16+qb)*16+kb; entries with kb>qb are never
// written and stay zero (BSS zero-init), so predicated-zero weights are safe.
__device__ float g_po[NH * NQB * NQB * 32 * 64];   // 16.8 MB (L2-resident)
__device__ float g_pm[NH * NQB * NQB * 32];
__device__ float g_pl[NH * NQB * NQB * 32];

__device__ __forceinline__ float warp_sum(float v) {
#pragma unroll
    for (int s = 16; s; s >>= 1) v += __shfl_xor_sync(0xffffffffu, v, s);
    return v;
}
__device__ __forceinline__ float softplusf(float x) {
    return (x > 20.f) ? x : log1pf(__expf(x));
}

// ---------------------------------------------------------------------------
// Kernel A: logmap0 row scale.
// ---------------------------------------------------------------------------
__global__ void rowscale_kernel(const float* __restrict__ x,
                                const float* __restrict__ c_sphere) {
    int warp = threadIdx.x >> 5, lane = threadIdx.x & 31;
    int row = blockIdx.x * 8 + warp;
    const float4* xr = (const float4*)(x + row * DIM);
    float ss = 0.f;
#pragma unroll
    for (int q = 0; q < 4; q++) {
        float4 v = xr[lane + q * 32];
        ss += v.x * v.x + v.y * v.y + v.z * v.z + v.w * v.w;
    }
    ss = warp_sum(ss);
    if (lane == 0) {
        float yn = sqrtf(ss);
        float sc = fmaxf(sqrtf(c_sphere[0]), EPS);
        float s = 0.f;
        if (yn >= EPS)
            s = atanhf(fminf(yn, ONE_M_EPS)) / (sc * fmaxf(yn, EPS));
        g_scale[row] = s;
    }
}

// ---------------------------------------------------------------------------
// Tiled fp32 GEMM with FFMA2 inner loop.
// BM=BN=64, BK=16, 256 threads, 4x4 per thread (as 4x2 f32x2 accumulators).
// ---------------------------------------------------------------------------
template <bool HAS_SCALE>
__global__ void gemm_kernel(const float* __restrict__ A, const float* __restrict__ B,
                            const float* __restrict__ bias,
                            const float* __restrict__ rowscale,
                            float* __restrict__ C, int M, int N, int K) {
    __shared__ float As[16][68];
    __shared__ float Bs[16][64];
    int tid = threadIdx.x;
    int tx = tid & 15, ty = tid >> 4;
    int m0 = blockIdx.y * 64, n0 = blockIdx.x * 64;
    int aRow = tid >> 2, aCol = (tid & 3) * 4;
    int bRow = tid >> 4, bCol = (tid & 15) * 4;
    u64 accP[4][2] = {};
    float ascale = 1.f;
    if (HAS_SCALE) ascale = rowscale[m0 + aRow];

    for (int kb = 0; kb < K; kb += 16) {
        float4 a4 = *(const float4*)(A + (size_t)(m0 + aRow) * K + kb + aCol);
        if (HAS_SCALE) { a4.x *= ascale; a4.y *= ascale; a4.z *= ascale; a4.w *= ascale; }
        As[aCol + 0][aRow] = a4.x;
        As[aCol + 1][aRow] = a4.y;
        As[aCol + 2][aRow] = a4.z;
        As[aCol + 3][aRow] = a4.w;
        *(float4*)&Bs[bRow][bCol] =
            *(const float4*)(B + (size_t)(kb + bRow) * N + n0 + bCol);
        __syncthreads();
#pragma unroll
        for (int k = 0; k < 16; k++) {
            float4 av = *(float4*)&As[k][ty * 4];
            float4 b4 = *(float4*)&Bs[k][tx * 4];
            u64 b01 = pack2(b4.x, b4.y);
            u64 b23 = pack2(b4.z, b4.w);
            u64 a0 = pack2(av.x, av.x);
            u64 a1 = pack2(av.y, av.y);
            u64 a2 = pack2(av.z, av.z);
            u64 a3 = pack2(av.w, av.w);
            accP[0][0] = ffma2(a0, b01, accP[0][0]);
            accP[0][1] = ffma2(a0, b23, accP[0][1]);
            accP[1][0] = ffma2(a1, b01, accP[1][0]);
            accP[1][1] = ffma2(a1, b23, accP[1][1]);
            accP[2][0] = ffma2(a2, b01, accP[2][0]);
            accP[2][1] = ffma2(a2, b23, accP[2][1]);
            accP[3][0] = ffma2(a3, b01, accP[3][0]);
            accP[3][1] = ffma2(a3, b23, accP[3][1]);
        }
        __syncthreads();
    }
    float4 bv = *(const float4*)(bias + n0 + tx * 4);
#pragma unroll
    for (int i = 0; i < 4; i++) {
        float4 o;
        unpack2(accP[i][0], o.x, o.y);
        unpack2(accP[i][1], o.z, o.w);
        o.x += bv.x; o.y += bv.y; o.z += bv.z; o.w += bv.w;
        *(float4*)(C + (size_t)(m0 + ty * 4 + i) * N + n0 + tx * 4) = o;
    }
}

// ---------------------------------------------------------------------------
// Kernel C: RoPE + expmap0 + norms (unchanged)
// ---------------------------------------------------------------------------
__global__ void rope_expmap_kernel(const float* __restrict__ freqs,
                                   const float* __restrict__ c_logits) {
    int warp = threadIdx.x >> 5, lane = threadIdx.x & 31;
    int idx = blockIdx.x * 8 + warp;   // 0..4095
    int h = idx & 7, n = idx >> 3;
    float c = softplusf(c_logits[h]);
    float sc = fmaxf(sqrtf(c), EPS);
    float f = freqs[n * 32 + lane];
    float cs = cosf(f), sn = sinf(f);
    const float* base = g_qkv + (size_t)n * 1536 + h * 64;
#pragma unroll
    for (int w = 0; w < 2; w++) {   // w=0: q, w=1: k
        const float* src = base + w * DIM;
        float xr = src[lane], xi = src[lane + 32];
        float r0 = xr * cs - xi * sn;
        float r1 = xr * sn + xi * cs;
        float vn = sqrtf(warp_sum(r0 * r0 + r1 * r1));
        float mag = tanhf(sc * vn) / sc;
        float s = (vn < EPS) ? 0.f : mag / fmaxf(vn, EPS);
        if (mag >= 1.0f) s *= ONE_M_EPS / fmaxf(mag, EPS);  // _project
        float o0 = r0 * s, o1 = r1 * s;
        float x2 = warp_sum(o0 * o0 + o1 * o1);
        float* dst = (w == 0 ? g_qh : g_kh) + (size_t)(h * NSEQ + n) * HD;
        dst[lane] = o0;
        dst[lane + 32] = o1;
        if (lane == 0) (w == 0 ? g_q2 : g_k2)[h * NSEQ + n] = x2;
    }
}

// ---------------------------------------------------------------------------
// Kernel D v3, pass 1: split-K partial attention, FFMA2 score + PV.
// grid (136, 8): blockIdx.x = triangular tile index (qb,kb), kb <= qb.
// ---------------------------------------------------------------------------
__device__ __forceinline__ float hyp_score(float dot, float q2, float k2, float b,
                                           float c, float c2, float sc,
                                           float neg_gs2sc) {
    float xy = -dot;
    float t2 = 2.f * c * xy;
    float a = 1.f + t2 + c * k2;
    float den = 1.f + t2 + c2 * q2 * k2;
    float num2 = fmaxf(a * a * q2 + 2.f * a * b * xy + b * b * k2, 0.f);
    float nrm = sqrtf(num2) / fmaxf(den, EPS);
    if (nrm >= 1.f) nrm = ONE_M_EPS;                    // _project
    float arg = fminf(sc * nrm, ONE_M_EPS);
    float at = 0.5f * __logf(__fdividef(1.f + arg, 1.f - arg));
    return neg_gs2sc * at;
}

__global__ __launch_bounds__(256) void attn_part_kernel(const float* __restrict__ c_logits,
                                                        const float* __restrict__ geo_scale) {
    __shared__ float Qs[32][68];
    __shared__ float Ks[32][68];
    __shared__ float Vs[32][68];
    __shared__ float Ss[32][36];
    __shared__ float q2s[32], k2s[32], bs[32];

    int tid = threadIdx.x;
    int lane = tid & 31, warp = tid >> 5;
    int h = blockIdx.y;
    int t = blockIdx.x;
    // triangular decode with integer fixup
    int qb = (int)floorf((sqrtf(8.f * t + 1.f) - 1.f) * 0.5f);
    while ((qb + 1) * (qb + 2) / 2 <= t) qb++;
    while (qb * (qb + 1) / 2 > t) qb--;
    int kb = t - qb * (qb + 1) / 2;

    float c = softplusf(c_logits[h]);
    float sc = fmaxf(sqrtf(c), EPS);
    float gs = geo_scale[h];
    float c2 = c * c;
    float neg_gs2sc = -gs * 2.0f / sc;

    // ---- stage Q, K, V, stats ----
    {
        const float* qbase = g_qh + ((size_t)h * NSEQ + qb * 32) * HD;
        const float* kbase = g_kh + ((size_t)h * NSEQ + kb * 32) * HD;
        const float* vbase = g_qkv + (size_t)(kb * 32) * 1536 + 2 * DIM + h * 64;
#pragma unroll
        for (int e = tid; e < 512; e += 256) {       // float4 units
            int row = e >> 4, dc = e & 15;
            *(float4*)&Qs[row][dc * 4] = *(const float4*)(qbase + row * 64 + dc * 4);
            *(float4*)&Ks[row][dc * 4] = *(const float4*)(kbase + row * 64 + dc * 4);
            *(float4*)&Vs[row][dc * 4] = *(const float4*)(vbase + (size_t)row * 1536 + dc * 4);
        }
        if (tid < 32) {
            float q2 = g_q2[h * NSEQ + qb * 32 + tid];
            q2s[tid] = q2;
            bs[tid] = 1.f - c * q2;
            k2s[tid] = g_k2[h * NSEQ + kb * 32 + tid];
        }
    }
    __syncthreads();

    // ---- score phase: 2x2 micro-tile, f32x2 packed dot products ----
    int ty = tid >> 4, tx = tid & 15;
    u64 p00 = 0, p01 = 0, p10 = 0, p11 = 0;
#pragma unroll
    for (int dc = 0; dc < 16; dc++) {
        float4 qa = *(float4*)&Qs[ty][dc * 4];
        float4 qc = *(float4*)&Qs[ty + 16][dc * 4];
        float4 ka = *(float4*)&Ks[tx][dc * 4];
        float4 kc = *(float4*)&Ks[tx + 16][dc * 4];
        u64 qa01 = pack2(qa.x, qa.y), qa23 = pack2(qa.z, qa.w);
        u64 qc01 = pack2(qc.x, qc.y), qc23 = pack2(qc.z, qc.w);
        u64 ka01 = pack2(ka.x, ka.y), ka23 = pack2(ka.z, ka.w);
        u64 kc01 = pack2(kc.x, kc.y), kc23 = pack2(kc.z, kc.w);
        p00 = ffma2(qa01, ka01, p00); p00 = ffma2(qa23, ka23, p00);
        p01 = ffma2(qa01, kc01, p01); p01 = ffma2(qa23, kc23, p01);
        p10 = ffma2(qc01, ka01, p10); p10 = ffma2(qc23, ka23, p10);
        p11 = ffma2(qc01, kc01, p11); p11 = ffma2(qc23, kc23, p11);
    }
    float d00, d01, d10, d11;
    {
        float lo, hi;
        unpack2(p00, lo, hi); d00 = lo + hi;
        unpack2(p01, lo, hi); d01 = lo + hi;
        unpack2(p10, lo, hi); d10 = lo + hi;
        unpack2(p11, lo, hi); d11 = lo + hi;
    }
    {
        int qg0 = qb * 32 + ty, qg1 = qg0 + 16;
        int jg0 = kb * 32 + tx, jg1 = jg0 + 16;
        float q2a = q2s[ty], q2b = q2s[ty + 16];
        float ba = bs[ty], bb = bs[ty + 16];
        float k2a = k2s[tx], k2b = k2s[tx + 16];
        Ss[ty][tx]           = (jg0 <= qg0) ? hyp_score(d00, q2a, k2a, ba, c, c2, sc, neg_gs2sc) : -INFINITY;
        Ss[ty][tx + 16]      = (jg1 <= qg0) ? hyp_score(d01, q2a, k2b, ba, c, c2, sc, neg_gs2sc) : -INFINITY;
        Ss[ty + 16][tx]      = (jg0 <= qg1) ? hyp_score(d10, q2b, k2a, bb, c, c2, sc, neg_gs2sc) : -INFINITY;
        Ss[ty + 16][tx + 16] = (jg1 <= qg1) ? hyp_score(d11, q2b, k2b, bb, c, c2, sc, neg_gs2sc) : -INFINITY;
    }
    __syncthreads();

    int ti = (h * NQB + qb) * NQB + kb;

    // ---- local softmax: 8 lanes per row; write m, l, p ----
    {
        int sr = (warp << 2) + (lane >> 3), part = lane & 7;
        float4 s4 = *(float4*)&Ss[sr][part * 4];
        float mx = fmaxf(fmaxf(s4.x, s4.y), fmaxf(s4.z, s4.w));
#pragma unroll
        for (int d = 1; d < 8; d <<= 1)
            mx = fmaxf(mx, __shfl_xor_sync(0xffffffffu, mx, d));
        float4 p4;
        p4.x = __expf(s4.x - mx);
        p4.y = __expf(s4.y - mx);
        p4.z = __expf(s4.z - mx);
        p4.w = __expf(s4.w - mx);
        float ps = p4.x + p4.y + p4.z + p4.w;
#pragma unroll
        for (int d = 1; d < 8; d <<= 1)
            ps += __shfl_xor_sync(0xffffffffu, ps, d);
        *(float4*)&Ss[sr][part * 4] = p4;
        if (part == 0) {
            g_pm[ti * 32 + sr] = mx;
            g_pl[ti * 32 + sr] = ps;
        }
    }
    __syncthreads();

    // ---- PV partial: f32x2 accumulators ----
    {
        int pr = tid >> 3, pc = tid & 7;
        u64 oA01 = 0, oA23 = 0, oB01 = 0, oB23 = 0;
#pragma unroll
        for (int jj = 0; jj < 32; jj++) {
            float p = Ss[pr][jj];
            u64 pp = pack2(p, p);
            float4 v0 = *(float4*)&Vs[jj][pc * 4];
            float4 v1 = *(float4*)&Vs[jj][32 + pc * 4];
            oA01 = ffma2(pp, pack2(v0.x, v0.y), oA01);
            oA23 = ffma2(pp, pack2(v0.z, v0.w), oA23);
            oB01 = ffma2(pp, pack2(v1.x, v1.y), oB01);
            oB23 = ffma2(pp, pack2(v1.z, v1.w), oB23);
        }
        float4 oA, oB;
        unpack2(oA01, oA.x, oA.y); unpack2(oA23, oA.z, oA.w);
        unpack2(oB01, oB.x, oB.y); unpack2(oB23, oB.z, oB.w);
        float* dst = g_po + (size_t)ti * 2048 + pr * 64;
        *(float4*)(dst + pc * 4) = oA;
        *(float4*)(dst + 32 + pc * 4) = oB;
    }
}

// ---------------------------------------------------------------------------
// Kernel D v3, pass 2: combine partials, FULLY UNROLLED (unchanged from R14 —
// measured good as part of the 100.8us total).
// ---------------------------------------------------------------------------
__global__ __launch_bounds__(256) void attn_reduce_kernel() {
    int tid = threadIdx.x;
    int qb = blockIdx.x, h = blockIdx.y;
    int pr = tid >> 3, pc = tid & 7;
    int tibase = (h * NQB + qb) * NQB;

    float mv[NQB], lv[NQB];
#pragma unroll
    for (int kb = 0; kb < NQB; kb++) {
        mv[kb] = g_pm[(tibase + kb) * 32 + pr];    // always in-bounds
        lv[kb] = g_pl[(tibase + kb) * 32 + pr];
    }
    float M = -INFINITY;
#pragma unroll
    for (int kb = 0; kb < NQB; kb++)
        M = fmaxf(M, (kb <= qb) ? mv[kb] : -INFINITY);

    float w[NQB];
    float L = 0.f;
#pragma unroll
    for (int kb = 0; kb < NQB; kb++) {
        w[kb] = (kb <= qb) ? __expf(mv[kb] - M) : 0.f;
        L += w[kb] * lv[kb];
    }

    float4 oA = {0.f, 0.f, 0.f, 0.f}, oB = {0.f, 0.f, 0.f, 0.f};
#pragma unroll
    for (int kb = 0; kb < NQB; kb++) {
        const float* src = g_po + (size_t)(tibase + kb) * 2048 + pr * 64;
        float4 a = *(const float4*)(src + pc * 4);
        float4 b = *(const float4*)(src + 32 + pc * 4);
        float ww = w[kb];
        oA.x += ww * a.x; oA.y += ww * a.y; oA.z += ww * a.z; oA.w += ww * a.w;
        oB.x += ww * b.x; oB.y += ww * b.y; oB.z += ww * b.z; oB.w += ww * b.w;
    }

    float invl = __frcp_rn(L);
    int n = qb * 32 + pr;
    float* dst = g_attn + (size_t)n * DIM + h * 64;
    oA.x *= invl; oA.y *= invl; oA.z *= invl; oA.w *= invl;
    oB.x *= invl; oB.y *= invl; oB.z *= invl; oB.w *= invl;
    *(float4*)(dst + pc * 4) = oA;
    *(float4*)(dst + 32 + pc * 4) = oB;
}

// ---------------------------------------------------------------------------
extern "C" void kernel_launch(void* const* d_in, const int* in_sizes, int n_in,
                              void* d_out, int out_size) {
    const float* x_hyp    = (const float*)d_in[0];
    const float* freqs    = (const float*)d_in[1];
    const float* c_sphere = (const float*)d_in[2];
    const float* w_qkv    = (const float*)d_in[3];
    const float* b_qkv    = (const float*)d_in[4];
    const float* w_out    = (const float*)d_in[5];
    const float* b_out    = (const float*)d_in[6];
    const float* c_logits = (const float*)d_in[7];
    const float* geo      = (const float*)d_in[8];
    float* out = (float*)d_out;

    void *p_qkv = nullptr, *p_attn = nullptr, *p_scale = nullptr;
    cudaGetSymbolAddress(&p_qkv, g_qkv);
    cudaGetSymbolAddress(&p_attn, g_attn);
    cudaGetSymbolAddress(&p_scale, g_scale);

    // 1. logmap0 row scales
    rowscale_kernel<<<64, 256>>>(x_hyp, c_sphere);
    // 2. qkv = (x_hyp * scale) @ w_qkv + b_qkv   (M=512, N=1536, K=512)
    gemm_kernel<true><<<dim3(24, 8), 256>>>(x_hyp, w_qkv, b_qkv,
                                            (const float*)p_scale,
                                            (float*)p_qkv, NSEQ, 3 * DIM, DIM);
    // 3. RoPE + expmap0 + norms
    rope_expmap_kernel<<<512, 256>>>(freqs, c_logits);
    // 4a. split-K partial attention (136 causal tiles x 8 heads)
    attn_part_kernel<<<dim3(136, 8), 256>>>(c_logits, geo);
    // 4b. combine partials (fully unrolled)
    attn_reduce_kernel<<<dim3(16, 8), 256>>>();
    // 5. out = attn_out @ w_out + b_out   (M=N=K=512)
    gemm_kernel<false><<<dim3(8, 8), 256>>>((const float*)p_attn, w_out, b_out,
                                            nullptr, out, NSEQ, DIM, DIM);
}